// round 15
// baseline (speedup 1.0000x reference)
#include <cuda_runtime.h>
#include <math.h>
#include <stdint.h>

#define BB 2
#define SS 2048
#define DD 1024
#define HH 16
#define HD 64
#define MTOT (BB*SS)   // 4096 rows
#define QKVN 3072      // fused QKV output width

// ---------------------------------------------------------------------------
// Scratch (allocation-free rule: device globals) — fp32 holding tf32-rounded
// ---------------------------------------------------------------------------
__device__ float g_xt[MTOT*DD];          // x, tf32-rounded
__device__ float g_wt[4*DD*DD];          // Wq|Wk|Wv|Wo, tf32-rounded
__device__ float g_qkv[MTOT*QKVN];       // Q,K in [m][3072] (V third unused)
__device__ float g_vt[BB*HH*HD*SS];      // V transposed: [b][h][d][s]
__device__ float g_att[MTOT*DD];         // attention output, tf32-rounded

// ---------------------------------------------------------------------------
// PTX helpers
// ---------------------------------------------------------------------------
__device__ __forceinline__ uint32_t smem_u32(const void* p) {
    uint32_t a;
    asm("{ .reg .u64 t; cvta.to.shared.u64 t, %1; cvt.u32.u64 %0, t; }"
        : "=r"(a) : "l"(p));
    return a;
}
#define CP16(s, g) \
    asm volatile("cp.async.cg.shared.global [%0], [%1], 16;" \
                 :: "r"(s), "l"(g) : "memory")
#define CP_COMMIT() asm volatile("cp.async.commit_group;" ::: "memory")
#define CP_WAIT0()  asm volatile("cp.async.wait_group 0;" ::: "memory")
#define LDSM4(r, addr) \
    asm volatile("ldmatrix.sync.aligned.m8n8.x4.shared.b16 {%0,%1,%2,%3}, [%4];" \
                 : "=r"((r)[0]), "=r"((r)[1]), "=r"((r)[2]), "=r"((r)[3]) \
                 : "r"(addr))
#define MMA_TF32(c, a, b0, b1) \
    asm volatile("mma.sync.aligned.m16n8k8.row.col.f32.tf32.tf32.f32 " \
                 "{%0,%1,%2,%3}, {%4,%5,%6,%7}, {%8,%9}, {%0,%1,%2,%3};" \
                 : "+f"((c)[0]), "+f"((c)[1]), "+f"((c)[2]), "+f"((c)[3]) \
                 : "r"(__float_as_uint((a)[0])), "r"(__float_as_uint((a)[1])), \
                   "r"(__float_as_uint((a)[2])), "r"(__float_as_uint((a)[3])), \
                   "r"(__float_as_uint(b0)), "r"(__float_as_uint(b1)))
#define MMA_TF32U(c, a, b0, b1) \
    asm volatile("mma.sync.aligned.m16n8k8.row.col.f32.tf32.tf32.f32 " \
                 "{%0,%1,%2,%3}, {%4,%5,%6,%7}, {%8,%9}, {%0,%1,%2,%3};" \
                 : "+f"((c)[0]), "+f"((c)[1]), "+f"((c)[2]), "+f"((c)[3]) \
                 : "r"((a)[0]), "r"((a)[1]), "r"((a)[2]), "r"((a)[3]), \
                   "r"((b0)), "r"((b1)))

__device__ __forceinline__ float tf32r(float x) {
    float y;
    asm("cvt.rna.tf32.f32 %0, %1;" : "=f"(y) : "f"(x));
    return y;
}
__device__ __forceinline__ float fexp2(float x) {
    float y;
    asm("ex2.approx.ftz.f32 %0, %1;" : "=f"(y) : "f"(x));
    return y;
}

// ---------------------------------------------------------------------------
// Fused conversion: one launch rounds x AND all four weight matrices.
// Blocks [0, xn4/256)           -> x
// Blocks [xn4/256, +wtot4/256)  -> Wq|Wk|Wv|Wo (contiguous in g_wt)
// ---------------------------------------------------------------------------
__global__ void cvt_all_kernel(const float* __restrict__ x,
                               const float* __restrict__ w0,
                               const float* __restrict__ w1,
                               const float* __restrict__ w2,
                               const float* __restrict__ w3,
                               float* __restrict__ xt,
                               float* __restrict__ wt) {
    const int xn4 = MTOT * DD / 4;       // 1048576
    const int wn4 = DD * DD / 4;         // 262144
    int idx = blockIdx.x * blockDim.x + threadIdx.x;
    const float* src;
    float* dst;
    int i;
    if (idx < xn4) {
        src = x; dst = xt; i = idx;
    } else {
        int wi = idx - xn4;
        int w = wi / wn4;
        i = wi - w * wn4;
        src = (w == 0) ? w0 : (w == 1) ? w1 : (w == 2) ? w2 : w3;
        dst = wt + (size_t)w * (DD * DD / 4) * 4 / 4;   // w * wn4 float4s
        dst = wt;  // recompute below with float4 index
        i = wi;    // linear float4 index into g_wt
        src = nullptr;
        // fall through handled explicitly:
        const float* s = (w == 0) ? w0 : (w == 1) ? w1 : (w == 2) ? w2 : w3;
        float4 v = ((const float4*)s)[wi - w * wn4];
        v.x = tf32r(v.x); v.y = tf32r(v.y); v.z = tf32r(v.z); v.w = tf32r(v.w);
        ((float4*)wt)[wi] = v;
        return;
    }
    float4 v = ((const float4*)src)[i];
    v.x = tf32r(v.x); v.y = tf32r(v.y); v.z = tf32r(v.z); v.w = tf32r(v.w);
    ((float4*)dst)[i] = v;
}

// ---------------------------------------------------------------------------
// Persistent TF32 GEMM (R9 config — best measured): 256x128 CTA tile, BK=32,
// double-buffered cp.async, pre-rounded inputs, no in-loop cvt.
// OUTMODE 0: fp32 C.  OUTMODE 1: QKV with V tiles (n0>=2048) transposed.
// ---------------------------------------------------------------------------
#define GK 1024
#define GRS 144
#define GMS_A (256*GRS)
#define GMS_B (128*GRS)
#define GBUF (GMS_A + GMS_B)
#define GEMM_SMEM (2*GBUF)

__device__ __forceinline__ void issue_chunk(
    const float* __restrict__ A, const float* __restrict__ B,
    int m0, int n0, int kc, uint32_t sbuf, int tid)
{
    #pragma unroll
    for (int t = 0; t < 12; t++) {
        int idx = tid + t * 256;
        if (idx < 2048) {
            int row = idx >> 3, c4 = idx & 7;
            CP16(sbuf + row * GRS + c4 * 16,
                 A + (size_t)(m0 + row) * GK + kc + c4 * 4);
        } else {
            int v = idx - 2048;
            int row = v >> 3, c4 = v & 7;
            CP16(sbuf + GMS_A + row * GRS + c4 * 16,
                 B + (size_t)(n0 + row) * GK + kc + c4 * 4);
        }
    }
}

template<int OUTMODE>
__global__ __launch_bounds__(256, 1)
void gemm_tf32(const float* __restrict__ A, const float* __restrict__ B,
               float* __restrict__ C, float* __restrict__ vt,
               int ldc, int ntx, int ntiles)
{
    extern __shared__ char dsm[];
    const uint32_t sb = smem_u32(dsm);

    const int tid  = threadIdx.x;
    const int lane = tid & 31;
    const int wid  = tid >> 5;
    const int wm   = (wid >> 1) * 64;
    const int wn   = (wid & 1) * 64;

    const int t4   = lane >> 3;
    const int lrow = (lane & 7) + ((t4 & 1) << 3);
    const int kbo  = (t4 >> 1) << 4;
    const int r1   = lane >> 2;
    const int cc   = (lane & 3) * 2;

    for (int tile = blockIdx.x; tile < ntiles; tile += gridDim.x) {
        const int m0 = (tile / ntx) * 256;
        const int n0 = (tile % ntx) * 128;

        float acc[4][8][4];
        #pragma unroll
        for (int mt = 0; mt < 4; mt++)
            #pragma unroll
            for (int nt = 0; nt < 8; nt++)
                #pragma unroll
                for (int i = 0; i < 4; i++) acc[mt][nt][i] = 0.f;

        issue_chunk(A, B, m0, n0, 0, sb, tid);
        CP_COMMIT();

        const int NCH = GK / 32;
        for (int c = 0; c < NCH; c++) {
            CP_WAIT0();
            __syncthreads();
            if (c + 1 < NCH) {
                issue_chunk(A, B, m0, n0, (c + 1) * 32,
                            sb + ((c + 1) & 1) * GBUF, tid);
                CP_COMMIT();
            }
            const uint32_t bu = sb + (c & 1) * GBUF;

            #pragma unroll
            for (int ks = 0; ks < 4; ks++) {
                const uint32_t kbyte = ks * 32 + kbo;
                uint32_t af[4][4];
                #pragma unroll
                for (int mt = 0; mt < 4; mt++)
                    LDSM4(af[mt], bu + (wm + mt * 16 + lrow) * GRS + kbyte);
                #pragma unroll
                for (int np = 0; np < 4; np++) {
                    uint32_t bf[4];
                    LDSM4(bf, bu + GMS_A + (wn + np * 16 + lrow) * GRS + kbyte);
                    #pragma unroll
                    for (int mt = 0; mt < 4; mt++) {
                        MMA_TF32U(acc[mt][np * 2 + 0], af[mt], bf[0], bf[2]);
                        MMA_TF32U(acc[mt][np * 2 + 1], af[mt], bf[1], bf[3]);
                    }
                }
            }
            __syncthreads();
        }

        if (OUTMODE == 0 || n0 < 2048) {
            #pragma unroll
            for (int mt = 0; mt < 4; mt++) {
                #pragma unroll
                for (int nt = 0; nt < 8; nt++) {
                    size_t base = (size_t)(m0 + wm + mt * 16) * ldc
                                  + n0 + wn + nt * 8 + cc;
                    #pragma unroll
                    for (int r = 0; r < 2; r++) {
                        float p0 = acc[mt][nt][2*r], p1 = acc[mt][nt][2*r+1];
                        if (OUTMODE == 1) { p0 = tf32r(p0); p1 = tf32r(p1); }
                        *(float2*)&C[base + (size_t)(r1 + 8*r) * ldc] =
                            make_float2(p0, p1);
                    }
                }
            }
        } else {
            // V tiles: write transposed, tf32-rounded: vt[((b*16+h)*64+d)*2048+s]
            #pragma unroll
            for (int mt = 0; mt < 4; mt++) {
                #pragma unroll
                for (int nt = 0; nt < 8; nt++) {
                    int nb = n0 + wn + nt * 8 + cc;
                    #pragma unroll
                    for (int r = 0; r < 2; r++) {
                        int m = m0 + wm + mt * 16 + r1 + 8 * r;
                        int b = m >> 11, s = m & 2047;
                        #pragma unroll
                        for (int e = 0; e < 2; e++) {
                            int dg = nb + e - 2048;
                            int h = dg >> 6, d = dg & 63;
                            vt[(((size_t)b * 16 + h) * 64 + d) * 2048 + s] =
                                tf32r(acc[mt][nt][2*r + e]);
                        }
                    }
                }
            }
        }
    }
}

// ---------------------------------------------------------------------------
// TF32 flash attention — R12 config (best measured): 64q tiles, 128 threads,
// double buffer, 2 CTAs/SM, Q fragments held in registers.
// ---------------------------------------------------------------------------
#define ARS 272                  // smem row stride bytes (64 fp32 + 16 pad)
#define AKV (64*ARS)             // 17408 per K or VT tile
#define AT_BUF (2*AKV)           // 34816 (K + VT)
#define ATT_SMEM (AKV + 2*AT_BUF)   // Q + 2 buffers = 87040
#define SM_SCALE 0.18033688011112042f  // 0.125 * log2(e)

__global__ __launch_bounds__(128, 2)
void attn_tf32(const float* __restrict__ qkv, const float* __restrict__ vtg,
               float* __restrict__ att)
{
    extern __shared__ char dsm[];
    const uint32_t sQ  = smem_u32(dsm);
    const uint32_t sKV = sQ + AKV;

    const int tid  = threadIdx.x;
    const int lane = tid & 31;
    const int wid  = tid >> 5;
    const int qt   = gridDim.x - 1 - blockIdx.x;
    const int bh   = blockIdx.y;
    const int b    = bh >> 4;
    const int h    = bh & 15;
    const int q0   = qt * 64;

    const float* qbase = qkv + (size_t)b * SS * QKVN + h * HD;
    const float* kbase = qbase + DD;
    const float* vbase = vtg + ((size_t)bh * 64) * 2048;

    // ---- stage Q + first K/VT tile in one async group ----
    #pragma unroll
    for (int i = 0; i < 8; i++) {
        int idx = tid + i * 128;
        int row = idx >> 4, c4 = idx & 15;
        CP16(sQ + row * ARS + c4 * 16,
             qbase + (size_t)(q0 + row) * QKVN + c4 * 4);
    }
    #pragma unroll
    for (int i = 0; i < 16; i++) {
        int idx = tid + i * 128;
        int v   = idx & 1023;
        int row = v >> 4, c4 = v & 15;
        if (idx < 1024)
            CP16(sKV + row * ARS + c4 * 16,
                 kbase + (size_t)row * QKVN + c4 * 4);
        else
            CP16(sKV + AKV + row * ARS + c4 * 16,
                 vbase + (size_t)row * 2048 + c4 * 4);
    }
    CP_COMMIT();

    const int wq   = wid * 16;
    const int t4   = lane >> 3;
    const int lrow = (lane & 7) + ((t4 & 1) << 3);
    const int kbo  = (t4 >> 1) << 4;
    const int r1   = lane >> 2;
    const int c2   = (lane & 3) * 2;
    const int sA   = (lane & ~3) | ((lane & 3) >> 1);
    const int sB   = sA + 2;
    const int par  = lane & 1;

    float oacc[8][4];
    #pragma unroll
    for (int n = 0; n < 8; n++)
        #pragma unroll
        for (int i = 0; i < 4; i++) oacc[n][i] = 0.f;
    float mrow[2] = {-INFINITY, -INFINITY};
    float lrowv[2] = {0.f, 0.f};

    // ---- wait for Q + KV0; load Q frags ONCE into registers ----
    CP_WAIT0();
    __syncthreads();
    uint32_t qfr[8][4];
    #pragma unroll
    for (int kg = 0; kg < 8; kg++)
        LDSM4(qfr[kg], sQ + (wq + lrow) * ARS + kg * 32 + kbo);

    const int ntiles = qt + 1;
    for (int kt = 0; kt < ntiles; kt++) {
        if (kt + 1 < ntiles) {
            uint32_t nbuf = sKV + ((kt + 1) & 1) * AT_BUF;
            #pragma unroll
            for (int i = 0; i < 16; i++) {
                int idx = tid + i * 128;
                int v   = idx & 1023;
                int row = v >> 4, c4 = v & 15;
                if (idx < 1024)
                    CP16(nbuf + row * ARS + c4 * 16,
                         kbase + (size_t)((kt + 1) * 64 + row) * QKVN + c4 * 4);
                else
                    CP16(nbuf + AKV + row * ARS + c4 * 16,
                         vbase + (size_t)row * 2048 + (kt + 1) * 64 + c4 * 4);
            }
            CP_COMMIT();
        }
        const uint32_t buK = sKV + (kt & 1) * AT_BUF;
        const uint32_t buV = buK + AKV;

        // ---- S = Q K^T (Q from registers) ----
        float s[8][4];
        #pragma unroll
        for (int j = 0; j < 8; j++)
            #pragma unroll
            for (int i = 0; i < 4; i++) s[j][i] = 0.f;

        #pragma unroll
        for (int kg = 0; kg < 8; kg++) {
            const uint32_t kbyte = kg * 32 + kbo;
            #pragma unroll
            for (int j2 = 0; j2 < 4; j2++) {
                uint32_t kf[4];
                LDSM4(kf, buK + (j2 * 16 + lrow) * ARS + kbyte);
                MMA_TF32U(s[j2 * 2 + 0], qfr[kg], kf[0], kf[2]);
                MMA_TF32U(s[j2 * 2 + 1], qfr[kg], kf[1], kf[3]);
            }
        }

        // ---- scale (exp2 domain) + causal mask (diagonal tile) ----
        const bool masked = (kt == ntiles - 1);
        #pragma unroll
        for (int j = 0; j < 8; j++) {
            #pragma unroll
            for (int i = 0; i < 4; i++) {
                float sv = s[j][i] * SM_SCALE;
                if (masked) {
                    int qrow = wq + r1 + ((i >> 1) << 3);
                    int key  = j * 8 + c2 + (i & 1);
                    if (key > qrow) sv = -INFINITY;
                }
                s[j][i] = sv;
            }
        }

        // ---- online softmax (exp2 domain) ----
        #pragma unroll
        for (int r = 0; r < 2; r++) {
            float mx = -INFINITY;
            #pragma unroll
            for (int j = 0; j < 8; j++)
                mx = fmaxf(mx, fmaxf(s[j][2*r], s[j][2*r+1]));
            mx = fmaxf(mx, __shfl_xor_sync(0xffffffffu, mx, 1));
            mx = fmaxf(mx, __shfl_xor_sync(0xffffffffu, mx, 2));
            float mnew  = fmaxf(mrow[r], mx);
            float alpha = fexp2(mrow[r] - mnew);
            float psum = 0.f;
            #pragma unroll
            for (int j = 0; j < 8; j++) {
                float p0 = fexp2(s[j][2*r]   - mnew);
                float p1 = fexp2(s[j][2*r+1] - mnew);
                s[j][2*r] = p0; s[j][2*r+1] = p1;
                psum += p0 + p1;
            }
            psum += __shfl_xor_sync(0xffffffffu, psum, 1);
            psum += __shfl_xor_sync(0xffffffffu, psum, 2);
            lrowv[r] = lrowv[r] * alpha + psum;
            mrow[r] = mnew;
            #pragma unroll
            for (int n = 0; n < 8; n++) {
                oacc[n][2*r]   *= alpha;
                oacc[n][2*r+1] *= alpha;
            }
        }

        // ---- O += P V (P rearranged via shfl; V from VT tile) ----
        #pragma unroll
        for (int kg = 0; kg < 8; kg++) {
            float pa[4];
            {
                float e0 = __shfl_sync(0xffffffffu, s[kg][0], sA);
                float e1 = __shfl_sync(0xffffffffu, s[kg][1], sA);
                float e2 = __shfl_sync(0xffffffffu, s[kg][2], sA);
                float e3 = __shfl_sync(0xffffffffu, s[kg][3], sA);
                float f0 = __shfl_sync(0xffffffffu, s[kg][0], sB);
                float f1 = __shfl_sync(0xffffffffu, s[kg][1], sB);
                float f2 = __shfl_sync(0xffffffffu, s[kg][2], sB);
                float f3 = __shfl_sync(0xffffffffu, s[kg][3], sB);
                pa[0] = tf32r(par ? e1 : e0);
                pa[1] = tf32r(par ? e3 : e2);
                pa[2] = tf32r(par ? f1 : f0);
                pa[3] = tf32r(par ? f3 : f2);
            }
            const uint32_t kbyte = kg * 32 + kbo;
            #pragma unroll
            for (int n2 = 0; n2 < 4; n2++) {
                uint32_t vf[4];
                LDSM4(vf, buV + (n2 * 16 + lrow) * ARS + kbyte);
                MMA_TF32(oacc[n2 * 2 + 0], pa, __uint_as_float(vf[0]),
                                               __uint_as_float(vf[2]));
                MMA_TF32(oacc[n2 * 2 + 1], pa, __uint_as_float(vf[1]),
                                               __uint_as_float(vf[3]));
            }
        }

        if (kt + 1 < ntiles) {
            CP_WAIT0();
            __syncthreads();
        }
    }

    // ---- epilogue: normalize, tf32-round, store fp32 ----
    #pragma unroll
    for (int r = 0; r < 2; r++) {
        float linv = 1.f / lrowv[r];
        int qrow = q0 + wq + r1 + 8 * r;
        size_t base = (size_t)(b * SS + qrow) * DD + h * HD + c2;
        #pragma unroll
        for (int n = 0; n < 8; n++) {
            float p0 = tf32r(oacc[n][2*r] * linv);
            float p1 = tf32r(oacc[n][2*r+1] * linv);
            *(float2*)&att[base + n * 8] = make_float2(p0, p1);
        }
    }
}

// ---------------------------------------------------------------------------
extern "C" void kernel_launch(void* const* d_in, const int* in_sizes, int n_in,
                              void* d_out, int out_size) {
    const float* x  = (const float*)d_in[0];
    const float* Wq = (const float*)d_in[1];
    const float* Wk = (const float*)d_in[2];
    const float* Wv = (const float*)d_in[3];
    const float* Wo = (const float*)d_in[4];
    float* out = (float*)d_out;

    void *p_xt, *p_wt, *p_qkv, *p_vt, *p_att;
    cudaGetSymbolAddress(&p_xt, g_xt);
    cudaGetSymbolAddress(&p_wt, g_wt);
    cudaGetSymbolAddress(&p_qkv, g_qkv);
    cudaGetSymbolAddress(&p_vt, g_vt);
    cudaGetSymbolAddress(&p_att, g_att);

    float* xt  = (float*)p_xt;
    float* wt  = (float*)p_wt;
    float* qkv = (float*)p_qkv;
    float* vt  = (float*)p_vt;
    float* att = (float*)p_att;

    const int xn4 = MTOT * DD / 4;       // 1048576
    const int wtot4 = 4 * DD * DD / 4;   // 1048576
    // Single fused conversion launch for x + all four weight matrices
    cvt_all_kernel<<<(xn4 + wtot4) / 256, 256>>>(x, Wq, Wk, Wv, Wo, xt, wt);

    cudaFuncSetAttribute(gemm_tf32<0>,
                         cudaFuncAttributeMaxDynamicSharedMemorySize, GEMM_SMEM);
    cudaFuncSetAttribute(gemm_tf32<1>,
                         cudaFuncAttributeMaxDynamicSharedMemorySize, GEMM_SMEM);
    cudaFuncSetAttribute(attn_tf32,
                         cudaFuncAttributeMaxDynamicSharedMemorySize, ATT_SMEM);

    // Fused QKV projection: 384 tiles (16m x 24n) over 148 persistent CTAs
    gemm_tf32<1><<<148, 256, GEMM_SMEM>>>(
        xt, wt, qkv, vt, QKVN, QKVN / 128, (MTOT / 256) * (QKVN / 128));

    attn_tf32<<<dim3(SS / 64, BB * HH), 128, ATT_SMEM>>>(qkv, vt, att);

    // O projection: 128 tiles (16m x 8n), one wave
    gemm_tf32<0><<<128, 256, GEMM_SMEM>>>(
        att, wt + 3*DD*DD, out, nullptr, DD, DD / 128, (MTOT / 256) * (DD / 128));
}

// round 16
// speedup vs baseline: 1.0064x; 1.0064x over previous
#include <cuda_runtime.h>
#include <math.h>
#include <stdint.h>

#define BB 2
#define SS 2048
#define DD 1024
#define HH 16
#define HD 64
#define MTOT (BB*SS)   // 4096 rows
#define QKVN 3072      // fused QKV output width

// ---------------------------------------------------------------------------
// Scratch (allocation-free rule: device globals) — fp32 holding tf32-rounded
// ---------------------------------------------------------------------------
__device__ float g_xt[MTOT*DD];          // x, tf32-rounded
__device__ float g_wt[4*DD*DD];          // Wq|Wk|Wv|Wo, tf32-rounded
__device__ float g_qkv[MTOT*QKVN];       // Q,K in [m][3072] (V third unused)
__device__ float g_vt[BB*HH*HD*SS];      // V transposed: [b][h][d][s]
__device__ float g_att[MTOT*DD];         // attention output, tf32-rounded

// ---------------------------------------------------------------------------
// PTX helpers
// ---------------------------------------------------------------------------
__device__ __forceinline__ uint32_t smem_u32(const void* p) {
    uint32_t a;
    asm("{ .reg .u64 t; cvta.to.shared.u64 t, %1; cvt.u32.u64 %0, t; }"
        : "=r"(a) : "l"(p));
    return a;
}
#define CP16(s, g) \
    asm volatile("cp.async.cg.shared.global [%0], [%1], 16;" \
                 :: "r"(s), "l"(g) : "memory")
#define CP_COMMIT() asm volatile("cp.async.commit_group;" ::: "memory")
#define CP_WAIT0()  asm volatile("cp.async.wait_group 0;" ::: "memory")
#define LDSM4(r, addr) \
    asm volatile("ldmatrix.sync.aligned.m8n8.x4.shared.b16 {%0,%1,%2,%3}, [%4];" \
                 : "=r"((r)[0]), "=r"((r)[1]), "=r"((r)[2]), "=r"((r)[3]) \
                 : "r"(addr))
#define STS64(addr, v0, v1) \
    asm volatile("st.shared.v2.f32 [%0], {%1, %2};" \
                 :: "r"(addr), "f"(v0), "f"(v1) : "memory")
#define MMA_TF32U(c, a, b0, b1) \
    asm volatile("mma.sync.aligned.m16n8k8.row.col.f32.tf32.tf32.f32 " \
                 "{%0,%1,%2,%3}, {%4,%5,%6,%7}, {%8,%9}, {%0,%1,%2,%3};" \
                 : "+f"((c)[0]), "+f"((c)[1]), "+f"((c)[2]), "+f"((c)[3]) \
                 : "r"((a)[0]), "r"((a)[1]), "r"((a)[2]), "r"((a)[3]), \
                   "r"((b0)), "r"((b1)))

__device__ __forceinline__ float tf32r(float x) {
    float y;
    asm("cvt.rna.tf32.f32 %0, %1;" : "=f"(y) : "f"(x));
    return y;
}
__device__ __forceinline__ float fexp2(float x) {
    float y;
    asm("ex2.approx.ftz.f32 %0, %1;" : "=f"(y) : "f"(x));
    return y;
}

// ---------------------------------------------------------------------------
// Round fp32 -> tf32 (stored as fp32) — R9's two flat kernels (fastest)
// ---------------------------------------------------------------------------
__global__ void cvt_kernel(const float* __restrict__ in, float* __restrict__ out,
                           int n4) {
    int i = blockIdx.x * blockDim.x + threadIdx.x;
    if (i >= n4) return;
    float4 v = ((const float4*)in)[i];
    v.x = tf32r(v.x); v.y = tf32r(v.y); v.z = tf32r(v.z); v.w = tf32r(v.w);
    ((float4*)out)[i] = v;
}

__global__ void wcvt_kernel(const float* __restrict__ w0, const float* __restrict__ w1,
                            const float* __restrict__ w2, const float* __restrict__ w3,
                            float* __restrict__ out) {
    const int wn4 = DD * DD / 4;
    int idx = blockIdx.x * blockDim.x + threadIdx.x;
    if (idx >= 4 * wn4) return;
    int w = idx / wn4, i = idx - w * wn4;
    const float* src = (w == 0) ? w0 : (w == 1) ? w1 : (w == 2) ? w2 : w3;
    float4 v = ((const float4*)src)[i];
    v.x = tf32r(v.x); v.y = tf32r(v.y); v.z = tf32r(v.z); v.w = tf32r(v.w);
    ((float4*)out)[idx] = v;
}

// ---------------------------------------------------------------------------
// Persistent TF32 GEMM (R9 config, best measured): 256x128 CTA tile, BK=32,
// double-buffered cp.async, pre-rounded inputs.
// OUTMODE 0: fp32 C.  OUTMODE 1: QKV with V tiles (n0>=2048) transposed.
// ---------------------------------------------------------------------------
#define GK 1024
#define GRS 144
#define GMS_A (256*GRS)
#define GMS_B (128*GRS)
#define GBUF (GMS_A + GMS_B)
#define GEMM_SMEM (2*GBUF)

__device__ __forceinline__ void issue_chunk(
    const float* __restrict__ A, const float* __restrict__ B,
    int m0, int n0, int kc, uint32_t sbuf, int tid)
{
    #pragma unroll
    for (int t = 0; t < 12; t++) {
        int idx = tid + t * 256;
        if (idx < 2048) {
            int row = idx >> 3, c4 = idx & 7;
            CP16(sbuf + row * GRS + c4 * 16,
                 A + (size_t)(m0 + row) * GK + kc + c4 * 4);
        } else {
            int v = idx - 2048;
            int row = v >> 3, c4 = v & 7;
            CP16(sbuf + GMS_A + row * GRS + c4 * 16,
                 B + (size_t)(n0 + row) * GK + kc + c4 * 4);
        }
    }
}

template<int OUTMODE>
__global__ __launch_bounds__(256, 1)
void gemm_tf32(const float* __restrict__ A, const float* __restrict__ B,
               float* __restrict__ C, float* __restrict__ vt,
               int ldc, int ntx, int ntiles)
{
    extern __shared__ char dsm[];
    const uint32_t sb = smem_u32(dsm);

    const int tid  = threadIdx.x;
    const int lane = tid & 31;
    const int wid  = tid >> 5;
    const int wm   = (wid >> 1) * 64;
    const int wn   = (wid & 1) * 64;

    const int t4   = lane >> 3;
    const int lrow = (lane & 7) + ((t4 & 1) << 3);
    const int kbo  = (t4 >> 1) << 4;
    const int r1   = lane >> 2;
    const int cc   = (lane & 3) * 2;

    for (int tile = blockIdx.x; tile < ntiles; tile += gridDim.x) {
        const int m0 = (tile / ntx) * 256;
        const int n0 = (tile % ntx) * 128;

        float acc[4][8][4];
        #pragma unroll
        for (int mt = 0; mt < 4; mt++)
            #pragma unroll
            for (int nt = 0; nt < 8; nt++)
                #pragma unroll
                for (int i = 0; i < 4; i++) acc[mt][nt][i] = 0.f;

        issue_chunk(A, B, m0, n0, 0, sb, tid);
        CP_COMMIT();

        const int NCH = GK / 32;
        for (int c = 0; c < NCH; c++) {
            CP_WAIT0();
            __syncthreads();
            if (c + 1 < NCH) {
                issue_chunk(A, B, m0, n0, (c + 1) * 32,
                            sb + ((c + 1) & 1) * GBUF, tid);
                CP_COMMIT();
            }
            const uint32_t bu = sb + (c & 1) * GBUF;

            #pragma unroll
            for (int ks = 0; ks < 4; ks++) {
                const uint32_t kbyte = ks * 32 + kbo;
                uint32_t af[4][4];
                #pragma unroll
                for (int mt = 0; mt < 4; mt++)
                    LDSM4(af[mt], bu + (wm + mt * 16 + lrow) * GRS + kbyte);
                #pragma unroll
                for (int np = 0; np < 4; np++) {
                    uint32_t bf[4];
                    LDSM4(bf, bu + GMS_A + (wn + np * 16 + lrow) * GRS + kbyte);
                    #pragma unroll
                    for (int mt = 0; mt < 4; mt++) {
                        MMA_TF32U(acc[mt][np * 2 + 0], af[mt], bf[0], bf[2]);
                        MMA_TF32U(acc[mt][np * 2 + 1], af[mt], bf[1], bf[3]);
                    }
                }
            }
            __syncthreads();
        }

        if (OUTMODE == 0 || n0 < 2048) {
            #pragma unroll
            for (int mt = 0; mt < 4; mt++) {
                #pragma unroll
                for (int nt = 0; nt < 8; nt++) {
                    size_t base = (size_t)(m0 + wm + mt * 16) * ldc
                                  + n0 + wn + nt * 8 + cc;
                    #pragma unroll
                    for (int r = 0; r < 2; r++) {
                        float p0 = acc[mt][nt][2*r], p1 = acc[mt][nt][2*r+1];
                        if (OUTMODE == 1) { p0 = tf32r(p0); p1 = tf32r(p1); }
                        *(float2*)&C[base + (size_t)(r1 + 8*r) * ldc] =
                            make_float2(p0, p1);
                    }
                }
            }
        } else {
            // V tiles: write transposed, tf32-rounded: vt[((b*16+h)*64+d)*2048+s]
            #pragma unroll
            for (int mt = 0; mt < 4; mt++) {
                #pragma unroll
                for (int nt = 0; nt < 8; nt++) {
                    int nb = n0 + wn + nt * 8 + cc;
                    #pragma unroll
                    for (int r = 0; r < 2; r++) {
                        int m = m0 + wm + mt * 16 + r1 + 8 * r;
                        int b = m >> 11, s = m & 2047;
                        #pragma unroll
                        for (int e = 0; e < 2; e++) {
                            int dg = nb + e - 2048;
                            int h = dg >> 6, d = dg & 63;
                            vt[(((size_t)b * 16 + h) * 64 + d) * 2048 + s] =
                                tf32r(acc[mt][nt][2*r + e]);
                        }
                    }
                }
            }
        }
    }
}

// ---------------------------------------------------------------------------
// TF32 flash attention — R12 skeleton (64q tiles, 128 threads, double buffer,
// 2 CTAs/SM, Q frags in registers) with the P shfl-pack replaced by a
// per-warp smem P-staging tile: 16 STS.64 + syncwarp + 8 LDSM per key tile.
// ---------------------------------------------------------------------------
#define ARS 272                  // smem row stride bytes (64 fp32 + 16 pad)
#define AKV (64*ARS)             // 17408 per K or VT tile
#define AT_BUF (2*AKV)           // 34816 (K + VT)
#define PW_BYTES (16*ARS)        // 4352 per-warp P staging (16 q-rows)
#define ATT_SMEM (AKV + 2*AT_BUF + 4*PW_BYTES)   // 104448
#define SM_SCALE 0.18033688011112042f  // 0.125 * log2(e)

__global__ __launch_bounds__(128, 2)
void attn_tf32(const float* __restrict__ qkv, const float* __restrict__ vtg,
               float* __restrict__ att)
{
    extern __shared__ char dsm[];
    const uint32_t sQ  = smem_u32(dsm);
    const uint32_t sKV = sQ + AKV;
    const uint32_t sP  = sKV + 2 * AT_BUF;   // 4 x PW_BYTES

    const int tid  = threadIdx.x;
    const int lane = tid & 31;
    const int wid  = tid >> 5;
    const int qt   = gridDim.x - 1 - blockIdx.x;
    const int bh   = blockIdx.y;
    const int b    = bh >> 4;
    const int h    = bh & 15;
    const int q0   = qt * 64;

    const float* qbase = qkv + (size_t)b * SS * QKVN + h * HD;
    const float* kbase = qbase + DD;
    const float* vbase = vtg + ((size_t)bh * 64) * 2048;

    // ---- stage Q + first K/VT tile in one async group ----
    #pragma unroll
    for (int i = 0; i < 8; i++) {
        int idx = tid + i * 128;
        int row = idx >> 4, c4 = idx & 15;
        CP16(sQ + row * ARS + c4 * 16,
             qbase + (size_t)(q0 + row) * QKVN + c4 * 4);
    }
    #pragma unroll
    for (int i = 0; i < 16; i++) {
        int idx = tid + i * 128;
        int v   = idx & 1023;
        int row = v >> 4, c4 = v & 15;
        if (idx < 1024)
            CP16(sKV + row * ARS + c4 * 16,
                 kbase + (size_t)row * QKVN + c4 * 4);
        else
            CP16(sKV + AKV + row * ARS + c4 * 16,
                 vbase + (size_t)row * 2048 + c4 * 4);
    }
    CP_COMMIT();

    const int wq   = wid * 16;
    const int t4   = lane >> 3;
    const int lrow = (lane & 7) + ((t4 & 1) << 3);
    const int kbo  = (t4 >> 1) << 4;
    const int r1   = lane >> 2;
    const int c2   = (lane & 3) * 2;
    const uint32_t pw  = sP + wid * PW_BYTES;            // this warp's P tile
    const uint32_t ps0 = pw + r1 * ARS + c2 * 4;         // row r1 store base
    const uint32_t ps1 = pw + (r1 + 8) * ARS + c2 * 4;   // row r1+8 store base

    float oacc[8][4];
    #pragma unroll
    for (int n = 0; n < 8; n++)
        #pragma unroll
        for (int i = 0; i < 4; i++) oacc[n][i] = 0.f;
    float mrow[2] = {-INFINITY, -INFINITY};
    float lrowv[2] = {0.f, 0.f};

    // ---- wait for Q + KV0; load Q frags ONCE into registers ----
    CP_WAIT0();
    __syncthreads();
    uint32_t qfr[8][4];
    #pragma unroll
    for (int kg = 0; kg < 8; kg++)
        LDSM4(qfr[kg], sQ + (wq + lrow) * ARS + kg * 32 + kbo);

    const int ntiles = qt + 1;
    for (int kt = 0; kt < ntiles; kt++) {
        if (kt + 1 < ntiles) {
            uint32_t nbuf = sKV + ((kt + 1) & 1) * AT_BUF;
            #pragma unroll
            for (int i = 0; i < 16; i++) {
                int idx = tid + i * 128;
                int v   = idx & 1023;
                int row = v >> 4, c4 = v & 15;
                if (idx < 1024)
                    CP16(nbuf + row * ARS + c4 * 16,
                         kbase + (size_t)((kt + 1) * 64 + row) * QKVN + c4 * 4);
                else
                    CP16(nbuf + AKV + row * ARS + c4 * 16,
                         vbase + (size_t)row * 2048 + (kt + 1) * 64 + c4 * 4);
            }
            CP_COMMIT();
        }
        const uint32_t buK = sKV + (kt & 1) * AT_BUF;
        const uint32_t buV = buK + AKV;

        // ---- S = Q K^T (Q from registers) ----
        float s[8][4];
        #pragma unroll
        for (int j = 0; j < 8; j++)
            #pragma unroll
            for (int i = 0; i < 4; i++) s[j][i] = 0.f;

        #pragma unroll
        for (int kg = 0; kg < 8; kg++) {
            const uint32_t kbyte = kg * 32 + kbo;
            #pragma unroll
            for (int j2 = 0; j2 < 4; j2++) {
                uint32_t kf[4];
                LDSM4(kf, buK + (j2 * 16 + lrow) * ARS + kbyte);
                MMA_TF32U(s[j2 * 2 + 0], qfr[kg], kf[0], kf[2]);
                MMA_TF32U(s[j2 * 2 + 1], qfr[kg], kf[1], kf[3]);
            }
        }

        // ---- scale (exp2 domain) + causal mask (diagonal tile) ----
        const bool masked = (kt == ntiles - 1);
        #pragma unroll
        for (int j = 0; j < 8; j++) {
            #pragma unroll
            for (int i = 0; i < 4; i++) {
                float sv = s[j][i] * SM_SCALE;
                if (masked) {
                    int qrow = wq + r1 + ((i >> 1) << 3);
                    int key  = j * 8 + c2 + (i & 1);
                    if (key > qrow) sv = -INFINITY;
                }
                s[j][i] = sv;
            }
        }

        // ---- online softmax (exp2 domain) ----
        #pragma unroll
        for (int r = 0; r < 2; r++) {
            float mx = -INFINITY;
            #pragma unroll
            for (int j = 0; j < 8; j++)
                mx = fmaxf(mx, fmaxf(s[j][2*r], s[j][2*r+1]));
            mx = fmaxf(mx, __shfl_xor_sync(0xffffffffu, mx, 1));
            mx = fmaxf(mx, __shfl_xor_sync(0xffffffffu, mx, 2));
            float mnew  = fmaxf(mrow[r], mx);
            float alpha = fexp2(mrow[r] - mnew);
            float psum = 0.f;
            #pragma unroll
            for (int j = 0; j < 8; j++) {
                float p0 = fexp2(s[j][2*r]   - mnew);
                float p1 = fexp2(s[j][2*r+1] - mnew);
                s[j][2*r] = p0; s[j][2*r+1] = p1;
                psum += p0 + p1;
            }
            psum += __shfl_xor_sync(0xffffffffu, psum, 1);
            psum += __shfl_xor_sync(0xffffffffu, psum, 2);
            lrowv[r] = lrowv[r] * alpha + psum;
            mrow[r] = mnew;
            #pragma unroll
            for (int n = 0; n < 8; n++) {
                oacc[n][2*r]   *= alpha;
                oacc[n][2*r+1] *= alpha;
            }
        }

        // ---- store P (tf32-rounded) to this warp's staging tile ----
        #pragma unroll
        for (int j = 0; j < 8; j++) {
            STS64(ps0 + j * 32, tf32r(s[j][0]), tf32r(s[j][1]));
            STS64(ps1 + j * 32, tf32r(s[j][2]), tf32r(s[j][3]));
        }
        __syncwarp();

        // ---- O += P V (P frags via ldmatrix from staging; V from VT) ----
        #pragma unroll
        for (int kg = 0; kg < 8; kg++) {
            const uint32_t kbyte = kg * 32 + kbo;
            uint32_t pf[4];
            LDSM4(pf, pw + lrow * ARS + kbyte);
            #pragma unroll
            for (int n2 = 0; n2 < 4; n2++) {
                uint32_t vf[4];
                LDSM4(vf, buV + (n2 * 16 + lrow) * ARS + kbyte);
                MMA_TF32U(oacc[n2 * 2 + 0], pf, vf[0], vf[2]);
                MMA_TF32U(oacc[n2 * 2 + 1], pf, vf[1], vf[3]);
            }
        }
        __syncwarp();   // staging reads done before next tile overwrites

        if (kt + 1 < ntiles) {
            CP_WAIT0();
            __syncthreads();
        }
    }

    // ---- epilogue: normalize, tf32-round, store fp32 ----
    #pragma unroll
    for (int r = 0; r < 2; r++) {
        float linv = 1.f / lrowv[r];
        int qrow = q0 + wq + r1 + 8 * r;
        size_t base = (size_t)(b * SS + qrow) * DD + h * HD + c2;
        #pragma unroll
        for (int n = 0; n < 8; n++) {
            float p0 = tf32r(oacc[n][2*r] * linv);
            float p1 = tf32r(oacc[n][2*r+1] * linv);
            *(float2*)&att[base + n * 8] = make_float2(p0, p1);
        }
    }
}

// ---------------------------------------------------------------------------
extern "C" void kernel_launch(void* const* d_in, const int* in_sizes, int n_in,
                              void* d_out, int out_size) {
    const float* x  = (const float*)d_in[0];
    const float* Wq = (const float*)d_in[1];
    const float* Wk = (const float*)d_in[2];
    const float* Wv = (const float*)d_in[3];
    const float* Wo = (const float*)d_in[4];
    float* out = (float*)d_out;

    void *p_xt, *p_wt, *p_qkv, *p_vt, *p_att;
    cudaGetSymbolAddress(&p_xt, g_xt);
    cudaGetSymbolAddress(&p_wt, g_wt);
    cudaGetSymbolAddress(&p_qkv, g_qkv);
    cudaGetSymbolAddress(&p_vt, g_vt);
    cudaGetSymbolAddress(&p_att, g_att);

    float* xt  = (float*)p_xt;
    float* wt  = (float*)p_wt;
    float* qkv = (float*)p_qkv;
    float* vt  = (float*)p_vt;
    float* att = (float*)p_att;

    const int xn4 = MTOT * DD / 4;
    const int wtot4 = 4 * DD * DD / 4;
    cvt_kernel<<<xn4 / 256, 256>>>(x, xt, xn4);
    wcvt_kernel<<<(wtot4 + 255) / 256, 256>>>(Wq, Wk, Wv, Wo, wt);

    cudaFuncSetAttribute(gemm_tf32<0>,
                         cudaFuncAttributeMaxDynamicSharedMemorySize, GEMM_SMEM);
    cudaFuncSetAttribute(gemm_tf32<1>,
                         cudaFuncAttributeMaxDynamicSharedMemorySize, GEMM_SMEM);
    cudaFuncSetAttribute(attn_tf32,
                         cudaFuncAttributeMaxDynamicSharedMemorySize, ATT_SMEM);

    // Fused QKV projection: 384 tiles (16m x 24n) over 148 persistent CTAs
    gemm_tf32<1><<<148, 256, GEMM_SMEM>>>(
        xt, wt, qkv, vt, QKVN, QKVN / 128, (MTOT / 256) * (QKVN / 128));

    attn_tf32<<<dim3(SS / 64, BB * HH), 128, ATT_SMEM>>>(qkv, vt, att);

    // O projection: 128 tiles (16m x 8n), one wave
    gemm_tf32<0><<<128, 256, GEMM_SMEM>>>(
        att, wt + 3*DD*DD, out, nullptr, DD, DD / 128, (MTOT / 256) * (DD / 128));
}

// round 17
// speedup vs baseline: 1.0202x; 1.0138x over previous
#include <cuda_runtime.h>
#include <math.h>
#include <stdint.h>

#define BB 2
#define SS 2048
#define DD 1024
#define HH 16
#define HD 64
#define MTOT (BB*SS)   // 4096 rows
#define QKVN 3072      // fused QKV output width

// ---------------------------------------------------------------------------
// Scratch (allocation-free rule: device globals) — fp32 holding tf32-rounded
// ---------------------------------------------------------------------------
__device__ float g_xt[MTOT*DD];          // x, tf32-rounded
__device__ float g_wt[4*DD*DD];          // Wq|Wk|Wv|Wo, tf32-rounded
__device__ float g_qkv[MTOT*QKVN];       // Q,K in [m][3072] (V third unused)
__device__ float g_vt[BB*HH*HD*SS];      // V transposed: [b][h][d][s]
__device__ float g_att[MTOT*DD];         // attention output, tf32-rounded

// ---------------------------------------------------------------------------
// PTX helpers (target-agnostic: tf32 mma.sync / ldmatrix / cp.async)
// ---------------------------------------------------------------------------
__device__ __forceinline__ uint32_t smem_u32(const void* p) {
    uint32_t a;
    asm("{ .reg .u64 t; cvta.to.shared.u64 t, %1; cvt.u32.u64 %0, t; }"
        : "=r"(a) : "l"(p));
    return a;
}
#define CP16(s, g) \
    asm volatile("cp.async.cg.shared.global [%0], [%1], 16;" \
                 :: "r"(s), "l"(g) : "memory")
#define CP_COMMIT() asm volatile("cp.async.commit_group;" ::: "memory")
#define CP_WAIT0()  asm volatile("cp.async.wait_group 0;" ::: "memory")
#define LDSM4(r, addr) \
    asm volatile("ldmatrix.sync.aligned.m8n8.x4.shared.b16 {%0,%1,%2,%3}, [%4];" \
                 : "=r"((r)[0]), "=r"((r)[1]), "=r"((r)[2]), "=r"((r)[3]) \
                 : "r"(addr))
#define MMA_TF32(c, a, b0, b1) \
    asm volatile("mma.sync.aligned.m16n8k8.row.col.f32.tf32.tf32.f32 " \
                 "{%0,%1,%2,%3}, {%4,%5,%6,%7}, {%8,%9}, {%0,%1,%2,%3};" \
                 : "+f"((c)[0]), "+f"((c)[1]), "+f"((c)[2]), "+f"((c)[3]) \
                 : "r"(__float_as_uint((a)[0])), "r"(__float_as_uint((a)[1])), \
                   "r"(__float_as_uint((a)[2])), "r"(__float_as_uint((a)[3])), \
                   "r"(__float_as_uint(b0)), "r"(__float_as_uint(b1)))
#define MMA_TF32U(c, a, b0, b1) \
    asm volatile("mma.sync.aligned.m16n8k8.row.col.f32.tf32.tf32.f32 " \
                 "{%0,%1,%2,%3}, {%4,%5,%6,%7}, {%8,%9}, {%0,%1,%2,%3};" \
                 : "+f"((c)[0]), "+f"((c)[1]), "+f"((c)[2]), "+f"((c)[3]) \
                 : "r"((a)[0]), "r"((a)[1]), "r"((a)[2]), "r"((a)[3]), \
                   "r"((b0)), "r"((b1)))

__device__ __forceinline__ float tf32r(float x) {
    float y;
    asm("cvt.rna.tf32.f32 %0, %1;" : "=f"(y) : "f"(x));
    return y;
}
__device__ __forceinline__ float fexp2(float x) {
    float y;
    asm("ex2.approx.ftz.f32 %0, %1;" : "=f"(y) : "f"(x));
    return y;
}

// ---------------------------------------------------------------------------
// Round fp32 -> tf32 (stored as fp32)
// ---------------------------------------------------------------------------
__global__ void cvt_kernel(const float* __restrict__ in, float* __restrict__ out,
                           int n4) {
    int i = blockIdx.x * blockDim.x + threadIdx.x;
    if (i >= n4) return;
    float4 v = ((const float4*)in)[i];
    v.x = tf32r(v.x); v.y = tf32r(v.y); v.z = tf32r(v.z); v.w = tf32r(v.w);
    ((float4*)out)[i] = v;
}

__global__ void wcvt_kernel(const float* __restrict__ w0, const float* __restrict__ w1,
                            const float* __restrict__ w2, const float* __restrict__ w3,
                            float* __restrict__ out) {
    const int wn4 = DD * DD / 4;
    int idx = blockIdx.x * blockDim.x + threadIdx.x;
    if (idx >= 4 * wn4) return;
    int w = idx / wn4, i = idx - w * wn4;
    const float* src = (w == 0) ? w0 : (w == 1) ? w1 : (w == 2) ? w2 : w3;
    float4 v = ((const float4*)src)[i];
    v.x = tf32r(v.x); v.y = tf32r(v.y); v.z = tf32r(v.z); v.w = tf32r(v.w);
    ((float4*)out)[idx] = v;
}

// ---------------------------------------------------------------------------
// Persistent TF32 GEMM: 256x128 CTA tile (8 warps as 4x2, warp tile 64x64),
// BK=32, double-buffered cp.async.
// OUTMODE 0: fp32 C.  OUTMODE 1: QKV with V tiles (n0>=2048) transposed.
// ---------------------------------------------------------------------------
#define GK 1024
#define GRS 144
#define GMS_A (256*GRS)
#define GMS_B (128*GRS)
#define GBUF (GMS_A + GMS_B)
#define GEMM_SMEM (2*GBUF)

__device__ __forceinline__ void issue_chunk(
    const float* __restrict__ A, const float* __restrict__ B,
    int m0, int n0, int kc, uint32_t sbuf, int tid)
{
    #pragma unroll
    for (int t = 0; t < 12; t++) {
        int idx = tid + t * 256;
        if (idx < 2048) {
            int row = idx >> 3, c4 = idx & 7;
            CP16(sbuf + row * GRS + c4 * 16,
                 A + (size_t)(m0 + row) * GK + kc + c4 * 4);
        } else {
            int v = idx - 2048;
            int row = v >> 3, c4 = v & 7;
            CP16(sbuf + GMS_A + row * GRS + c4 * 16,
                 B + (size_t)(n0 + row) * GK + kc + c4 * 4);
        }
    }
}

template<int OUTMODE>
__global__ __launch_bounds__(256, 1)
void gemm_tf32(const float* __restrict__ A, const float* __restrict__ B,
               float* __restrict__ C, float* __restrict__ vt,
               int ldc, int ntx, int ntiles)
{
    extern __shared__ char dsm[];
    const uint32_t sb = smem_u32(dsm);

    const int tid  = threadIdx.x;
    const int lane = tid & 31;
    const int wid  = tid >> 5;
    const int wm   = (wid >> 1) * 64;
    const int wn   = (wid & 1) * 64;

    const int t4   = lane >> 3;
    const int lrow = (lane & 7) + ((t4 & 1) << 3);
    const int kbo  = (t4 >> 1) << 4;
    const int r1   = lane >> 2;
    const int cc   = (lane & 3) * 2;

    for (int tile = blockIdx.x; tile < ntiles; tile += gridDim.x) {
        const int m0 = (tile / ntx) * 256;
        const int n0 = (tile % ntx) * 128;

        float acc[4][8][4];
        #pragma unroll
        for (int mt = 0; mt < 4; mt++)
            #pragma unroll
            for (int nt = 0; nt < 8; nt++)
                #pragma unroll
                for (int i = 0; i < 4; i++) acc[mt][nt][i] = 0.f;

        issue_chunk(A, B, m0, n0, 0, sb, tid);
        CP_COMMIT();

        const int NCH = GK / 32;
        for (int c = 0; c < NCH; c++) {
            CP_WAIT0();
            __syncthreads();
            if (c + 1 < NCH) {
                issue_chunk(A, B, m0, n0, (c + 1) * 32,
                            sb + ((c + 1) & 1) * GBUF, tid);
                CP_COMMIT();
            }
            const uint32_t bu = sb + (c & 1) * GBUF;

            #pragma unroll
            for (int ks = 0; ks < 4; ks++) {
                const uint32_t kbyte = ks * 32 + kbo;
                uint32_t af[4][4];
                #pragma unroll
                for (int mt = 0; mt < 4; mt++)
                    LDSM4(af[mt], bu + (wm + mt * 16 + lrow) * GRS + kbyte);
                #pragma unroll
                for (int np = 0; np < 4; np++) {
                    uint32_t bf[4];
                    LDSM4(bf, bu + GMS_A + (wn + np * 16 + lrow) * GRS + kbyte);
                    #pragma unroll
                    for (int mt = 0; mt < 4; mt++) {
                        MMA_TF32U(acc[mt][np * 2 + 0], af[mt], bf[0], bf[2]);
                        MMA_TF32U(acc[mt][np * 2 + 1], af[mt], bf[1], bf[3]);
                    }
                }
            }
            __syncthreads();
        }

        if (OUTMODE == 0 || n0 < 2048) {
            #pragma unroll
            for (int mt = 0; mt < 4; mt++) {
                #pragma unroll
                for (int nt = 0; nt < 8; nt++) {
                    size_t base = (size_t)(m0 + wm + mt * 16) * ldc
                                  + n0 + wn + nt * 8 + cc;
                    #pragma unroll
                    for (int r = 0; r < 2; r++) {
                        float p0 = acc[mt][nt][2*r], p1 = acc[mt][nt][2*r+1];
                        if (OUTMODE == 1) { p0 = tf32r(p0); p1 = tf32r(p1); }
                        *(float2*)&C[base + (size_t)(r1 + 8*r) * ldc] =
                            make_float2(p0, p1);
                    }
                }
            }
        } else {
            #pragma unroll
            for (int mt = 0; mt < 4; mt++) {
                #pragma unroll
                for (int nt = 0; nt < 8; nt++) {
                    int nb = n0 + wn + nt * 8 + cc;
                    #pragma unroll
                    for (int r = 0; r < 2; r++) {
                        int m = m0 + wm + mt * 16 + r1 + 8 * r;
                        int b = m >> 11, s = m & 2047;
                        #pragma unroll
                        for (int e = 0; e < 2; e++) {
                            int dg = nb + e - 2048;
                            int h = dg >> 6, d = dg & 63;
                            vt[(((size_t)b * 16 + h) * 64 + d) * 2048 + s] =
                                tf32r(acc[mt][nt][2*r + e]);
                        }
                    }
                }
            }
        }
    }
}

// ---------------------------------------------------------------------------
// TF32 flash attention — 64-row Q tiles, 128-thread CTAs, double buffer,
// 2 CTAs/SM (R9 champion configuration).
// ---------------------------------------------------------------------------
#define ARS 272                  // smem row stride bytes (64 fp32 + 16 pad)
#define AMAT (64*ARS)            // 17408 per tile
#define ATT_SMEM (AMAT + 2*2*AMAT)   // Q + 2 x (K,VT) = 87040
#define SM_SCALE 0.18033688011112042f  // 0.125 * log2(e)

__global__ __launch_bounds__(128, 2)
void attn_tf32(const float* __restrict__ qkv, const float* __restrict__ vtg,
               float* __restrict__ att)
{
    extern __shared__ char dsm[];
    const uint32_t sQ  = smem_u32(dsm);
    const uint32_t sKV = sQ + AMAT;

    const int tid  = threadIdx.x;
    const int lane = tid & 31;
    const int wid  = tid >> 5;
    const int qt   = gridDim.x - 1 - blockIdx.x;
    const int bh   = blockIdx.y;
    const int b    = bh >> 4;
    const int h    = bh & 15;
    const int q0   = qt * 64;

    const float* qbase = qkv + (size_t)b * SS * QKVN + h * HD;
    const float* kbase = qbase + DD;
    const float* vbase = vtg + ((size_t)bh * 64) * 2048;

    #pragma unroll
    for (int i = 0; i < 8; i++) {              // Q: 1024 CP16
        int idx = tid + i * 128;
        int row = idx >> 4, c4 = idx & 15;
        CP16(sQ + row * ARS + c4 * 16,
             qbase + (size_t)(q0 + row) * QKVN + c4 * 4);
    }
    #pragma unroll
    for (int i = 0; i < 16; i++) {             // K + VT: 2048 CP16
        int idx = tid + i * 128;
        int v   = idx & 1023;
        int row = v >> 4, c4 = v & 15;
        if (idx < 1024)
            CP16(sKV + row * ARS + c4 * 16,
                 kbase + (size_t)row * QKVN + c4 * 4);
        else
            CP16(sKV + AMAT + row * ARS + c4 * 16,
                 vbase + (size_t)row * 2048 + c4 * 4);
    }
    CP_COMMIT();

    const int wq   = wid * 16;
    const int t4   = lane >> 3;
    const int lrow = (lane & 7) + ((t4 & 1) << 3);
    const int kbo  = (t4 >> 1) << 4;
    const int r1   = lane >> 2;
    const int c2   = (lane & 3) * 2;
    const int sA   = (lane & ~3) | ((lane & 3) >> 1);
    const int sB   = sA + 2;
    const int par  = lane & 1;

    float oacc[8][4];
    #pragma unroll
    for (int n = 0; n < 8; n++)
        #pragma unroll
        for (int i = 0; i < 4; i++) oacc[n][i] = 0.f;
    float mrow[2] = {-INFINITY, -INFINITY};
    float lrowv[2] = {0.f, 0.f};

    const int ntiles = qt + 1;
    for (int kt = 0; kt < ntiles; kt++) {
        CP_WAIT0();
        __syncthreads();
        if (kt + 1 < ntiles) {
            uint32_t nbuf = sKV + ((kt + 1) & 1) * (2 * AMAT);
            #pragma unroll
            for (int i = 0; i < 16; i++) {
                int idx = tid + i * 128;
                int v   = idx & 1023;
                int row = v >> 4, c4 = v & 15;
                if (idx < 1024)
                    CP16(nbuf + row * ARS + c4 * 16,
                         kbase + (size_t)((kt + 1) * 64 + row) * QKVN + c4 * 4);
                else
                    CP16(nbuf + AMAT + row * ARS + c4 * 16,
                         vbase + (size_t)row * 2048 + (kt + 1) * 64 + c4 * 4);
            }
            CP_COMMIT();
        }
        const uint32_t buK = sKV + (kt & 1) * (2 * AMAT);
        const uint32_t buV = buK + AMAT;

        float s[8][4];
        #pragma unroll
        for (int j = 0; j < 8; j++)
            #pragma unroll
            for (int i = 0; i < 4; i++) s[j][i] = 0.f;

        #pragma unroll
        for (int kg = 0; kg < 8; kg++) {
            const uint32_t kbyte = kg * 32 + kbo;
            uint32_t qf[4];
            LDSM4(qf, sQ + (wq + lrow) * ARS + kbyte);
            #pragma unroll
            for (int j2 = 0; j2 < 4; j2++) {
                uint32_t kf[4];
                LDSM4(kf, buK + (j2 * 16 + lrow) * ARS + kbyte);
                MMA_TF32U(s[j2 * 2 + 0], qf, kf[0], kf[2]);
                MMA_TF32U(s[j2 * 2 + 1], qf, kf[1], kf[3]);
            }
        }

        const bool masked = (kt == ntiles - 1);
        #pragma unroll
        for (int j = 0; j < 8; j++) {
            #pragma unroll
            for (int i = 0; i < 4; i++) {
                float sv = s[j][i] * SM_SCALE;
                if (masked) {
                    int qrow = wq + r1 + ((i >> 1) << 3);
                    int key  = j * 8 + c2 + (i & 1);
                    if (key > qrow) sv = -INFINITY;
                }
                s[j][i] = sv;
            }
        }

        #pragma unroll
        for (int r = 0; r < 2; r++) {
            float mx = -INFINITY;
            #pragma unroll
            for (int j = 0; j < 8; j++)
                mx = fmaxf(mx, fmaxf(s[j][2*r], s[j][2*r+1]));
            mx = fmaxf(mx, __shfl_xor_sync(0xffffffffu, mx, 1));
            mx = fmaxf(mx, __shfl_xor_sync(0xffffffffu, mx, 2));
            float mnew  = fmaxf(mrow[r], mx);
            float alpha = fexp2(mrow[r] - mnew);
            float psum = 0.f;
            #pragma unroll
            for (int j = 0; j < 8; j++) {
                float p0 = fexp2(s[j][2*r]   - mnew);
                float p1 = fexp2(s[j][2*r+1] - mnew);
                s[j][2*r] = p0; s[j][2*r+1] = p1;
                psum += p0 + p1;
            }
            psum += __shfl_xor_sync(0xffffffffu, psum, 1);
            psum += __shfl_xor_sync(0xffffffffu, psum, 2);
            lrowv[r] = lrowv[r] * alpha + psum;
            mrow[r] = mnew;
            #pragma unroll
            for (int n = 0; n < 8; n++) {
                oacc[n][2*r]   *= alpha;
                oacc[n][2*r+1] *= alpha;
            }
        }

        #pragma unroll
        for (int kg = 0; kg < 8; kg++) {
            float pa[4];
            {
                float e0 = __shfl_sync(0xffffffffu, s[kg][0], sA);
                float e1 = __shfl_sync(0xffffffffu, s[kg][1], sA);
                float e2 = __shfl_sync(0xffffffffu, s[kg][2], sA);
                float e3 = __shfl_sync(0xffffffffu, s[kg][3], sA);
                float f0 = __shfl_sync(0xffffffffu, s[kg][0], sB);
                float f1 = __shfl_sync(0xffffffffu, s[kg][1], sB);
                float f2 = __shfl_sync(0xffffffffu, s[kg][2], sB);
                float f3 = __shfl_sync(0xffffffffu, s[kg][3], sB);
                pa[0] = tf32r(par ? e1 : e0);
                pa[1] = tf32r(par ? e3 : e2);
                pa[2] = tf32r(par ? f1 : f0);
                pa[3] = tf32r(par ? f3 : f2);
            }
            const uint32_t kbyte = kg * 32 + kbo;
            #pragma unroll
            for (int n2 = 0; n2 < 4; n2++) {
                uint32_t vf[4];
                LDSM4(vf, buV + (n2 * 16 + lrow) * ARS + kbyte);
                MMA_TF32(oacc[n2 * 2 + 0], pa, __uint_as_float(vf[0]),
                                               __uint_as_float(vf[2]));
                MMA_TF32(oacc[n2 * 2 + 1], pa, __uint_as_float(vf[1]),
                                               __uint_as_float(vf[3]));
            }
        }
    }

    #pragma unroll
    for (int r = 0; r < 2; r++) {
        float linv = 1.f / lrowv[r];
        int qrow = q0 + wq + r1 + 8 * r;
        size_t base = (size_t)(b * SS + qrow) * DD + h * HD + c2;
        #pragma unroll
        for (int n = 0; n < 8; n++) {
            float p0 = tf32r(oacc[n][2*r] * linv);
            float p1 = tf32r(oacc[n][2*r+1] * linv);
            *(float2*)&att[base + n * 8] = make_float2(p0, p1);
        }
    }
}

// ---------------------------------------------------------------------------
extern "C" void kernel_launch(void* const* d_in, const int* in_sizes, int n_in,
                              void* d_out, int out_size) {
    const float* x  = (const float*)d_in[0];
    const float* Wq = (const float*)d_in[1];
    const float* Wk = (const float*)d_in[2];
    const float* Wv = (const float*)d_in[3];
    const float* Wo = (const float*)d_in[4];
    float* out = (float*)d_out;

    void *p_xt, *p_wt, *p_qkv, *p_vt, *p_att;
    cudaGetSymbolAddress(&p_xt, g_xt);
    cudaGetSymbolAddress(&p_wt, g_wt);
    cudaGetSymbolAddress(&p_qkv, g_qkv);
    cudaGetSymbolAddress(&p_vt, g_vt);
    cudaGetSymbolAddress(&p_att, g_att);

    float* xt  = (float*)p_xt;
    float* wt  = (float*)p_wt;
    float* qkv = (float*)p_qkv;
    float* vt  = (float*)p_vt;
    float* att = (float*)p_att;

    const int xn4 = MTOT * DD / 4;
    const int wtot4 = 4 * DD * DD / 4;
    cvt_kernel<<<xn4 / 256, 256>>>(x, xt, xn4);
    wcvt_kernel<<<(wtot4 + 255) / 256, 256>>>(Wq, Wk, Wv, Wo, wt);

    cudaFuncSetAttribute(gemm_tf32<0>,
                         cudaFuncAttributeMaxDynamicSharedMemorySize, GEMM_SMEM);
    cudaFuncSetAttribute(gemm_tf32<1>,
                         cudaFuncAttributeMaxDynamicSharedMemorySize, GEMM_SMEM);

    // Fused QKV projection: 384 tiles (16m x 24n) over 148 persistent CTAs
    gemm_tf32<1><<<148, 256, GEMM_SMEM>>>(
        xt, wt, qkv, vt, QKVN, QKVN / 128, (MTOT / 256) * (QKVN / 128));

    cudaFuncSetAttribute(attn_tf32,
                         cudaFuncAttributeMaxDynamicSharedMemorySize, ATT_SMEM);
    attn_tf32<<<dim3(SS / 64, BB * HH), 128, ATT_SMEM>>>(qkv, vt, att);

    // O projection: 128 tiles (16m x 8n), one wave
    gemm_tf32<0><<<128, 256, GEMM_SMEM>>>(
        att, wt + 3*DD*DD, out, nullptr, DD, DD / 128, (MTOT / 256) * (DD / 128));
}